// round 7
// baseline (speedup 1.0000x reference)
#include <cuda_runtime.h>
#include <cuda_bf16.h>
#include <cuda_fp16.h>
#include <cstdint>

#define NB 4
#define NN 10000
#define NE 170000
#define FIN 256
#define FOUT 128
#define NH 4
#define MTOT (NB*NN)          /* 40000 */
#define CPN (NB*NH*FOUT)      /* 2048 values per node row */
#define LEAKY 0.2f

// ---------------- scratch (static device memory; no allocs allowed) --------
__device__ __half  d_h[(size_t)NN * CPN];      // h fp16, node-major [n][b][head][f] (41 MB)
__device__ float4  d_ev[NE];                   // exp(att) per edge, 4 heads packed
__device__ float4  d_ps[NN];
__device__ float4  d_pd[NN];
__device__ int     d_rowptr[NN + 1];
__device__ float   d_vsrc[NH * FIN];
__device__ float   d_vdst[NH * FIN];
__device__ float   d_csrc[NH];
__device__ float   d_cdst[NH];
// fp16 W transposed to [h][n][k] for the tensor-core GEMM
__device__ __half  d_Bf[NH * FOUT * FIN];

__device__ __forceinline__ uint32_t smem_u32(const void* p) {
    uint32_t a;
    asm("{ .reg .u64 t; cvta.to.shared.u64 t, %1; cvt.u32.u64 %0, t; }" : "=r"(a) : "l"(p));
    return a;
}
__device__ __forceinline__ void cp16(uint32_t saddr, const void* g) {
    asm volatile("cp.async.cg.shared.global [%0], [%1], 16;" :: "r"(saddr), "l"(g));
}
#define CP_COMMIT() asm volatile("cp.async.commit_group;" ::: "memory")
#define CP_WAIT0()  asm volatile("cp.async.wait_group 0;" ::: "memory")

// ---------------- K0: W fp16 transpose + attention-vector fold (fused) -----
__global__ void prep_all(const float* __restrict__ Wm, const float* __restrict__ bm,
                         const float* __restrict__ Wa) {
    if (blockIdx.x < 512) {
        int i = blockIdx.x * 256 + threadIdx.x;      // [h][k][f]
        int h = i >> 15;
        int rem = i & 32767;
        int k = rem >> 7;
        int f = rem & 127;
        size_t o = ((size_t)h * FOUT + f) * FIN + k; // [h][n][k]
        d_Bf[o] = __float2half_rn(Wm[i]);
        return;
    }
    int h = blockIdx.x - 512;
    int t = threadIdx.x;
    __shared__ float asrc[FOUT], adst[FOUT];
    if (t < FOUT) {
        asrc[t] = Wa[h * 2 * FOUT + t];
        adst[t] = Wa[h * 2 * FOUT + FOUT + t];
    }
    __syncthreads();
    const float* w = Wm + (size_t)h * FIN * FOUT + (size_t)t * FOUT;
    float s1 = 0.f, s2 = 0.f;
#pragma unroll 8
    for (int f = 0; f < FOUT; f++) {
        float wv = w[f];
        s1 += wv * asrc[f];
        s2 += wv * adst[f];
    }
    d_vsrc[h * FIN + t] = s1;
    d_vdst[h * FIN + t] = s2;
    if (t == 0) {
        float c1 = 0.f, c2 = 0.f;
        for (int f = 0; f < FOUT; f++) {
            float bv = bm[h * FOUT + f];
            c1 += bv * asrc[f];
            c2 += bv * adst[f];
        }
        d_csrc[h] = c1;
        d_cdst[h] = c2;
    }
}

// ---------------- K1: per-node scores, warp per node -----------------------
__global__ void node_scores(const float* __restrict__ Xl) {
    int gw = (blockIdx.x * blockDim.x + threadIdx.x) >> 5;
    int lane = threadIdx.x & 31;
    if (gw >= NN) return;
    const float* xr = Xl + (size_t)gw * FIN;
    float xv[8];
#pragma unroll
    for (int i = 0; i < 8; i++) xv[i] = xr[lane + 32 * i];
    float ps[NH], pd[NH];
#pragma unroll
    for (int h = 0; h < NH; h++) {
        float s1 = 0.f, s2 = 0.f;
#pragma unroll
        for (int i = 0; i < 8; i++) {
            int k = lane + 32 * i;
            s1 += xv[i] * d_vsrc[h * FIN + k];
            s2 += xv[i] * d_vdst[h * FIN + k];
        }
#pragma unroll
        for (int o = 16; o > 0; o >>= 1) {
            s1 += __shfl_down_sync(0xffffffffu, s1, o);
            s2 += __shfl_down_sync(0xffffffffu, s2, o);
        }
        ps[h] = s1;
        pd[h] = s2;
    }
    if (lane == 0) {
        d_ps[gw] = make_float4(ps[0] + d_csrc[0], ps[1] + d_csrc[1],
                               ps[2] + d_csrc[2], ps[3] + d_csrc[3]);
        d_pd[gw] = make_float4(pd[0] + d_cdst[0], pd[1] + d_cdst[1],
                               pd[2] + d_cdst[2], pd[3] + d_cdst[3]);
    }
}

// ---------------- K2: per-edge exp + CSR row_ptr (fused) -------------------
__device__ __forceinline__ float att_act(float s) {
    float lr = s > 0.f ? s : LEAKY * s;
    lr = fminf(fmaxf(lr, -2.f), 2.f);
    return expf(lr);
}

__global__ void edge_prep(const int* __restrict__ src, const int* __restrict__ dst) {
    int e = blockIdx.x * blockDim.x + threadIdx.x;
    if (e >= NE) return;
    int cur = src[e];
    float4 a = d_ps[cur];
    float4 b = d_pd[dst[e]];
    d_ev[e] = make_float4(att_act(a.x + b.x), att_act(a.y + b.y),
                          att_act(a.z + b.z), att_act(a.w + b.w));
    int prev = (e == 0) ? -1 : src[e - 1];
    for (int n = prev + 1; n <= cur; n++) d_rowptr[n] = e;
    if (e == NE - 1)
        for (int n = cur + 1; n <= NN; n++) d_rowptr[n] = NE;
}

// ---------------- K3: pipelined single-pass fp16 GEMM ----------------------
// CTA: 256 thr / 8 warps; tile M=128 x N=128 (one head); K chunk = 64.
// Double-buffered (2 x 36.9KB); A LDG+cvt reg-prefetch; B via cp.async.
#define GK 64
#define PADK 72                       /* padded k-stride (fp16) -> 144B rows  */
#define TILE_B (128 * PADK * 2)       /* 18432 bytes per smem tile */
#define STAGE_B (2 * TILE_B)          /* A + B per stage = 36864 */
#define OFF_A 0
#define OFF_B (TILE_B)
#define SM_TOTAL (2 * STAGE_B)        /* 73728 */

#define MMA_F16(d, a, b)                                                       \
    asm volatile("mma.sync.aligned.m16n8k16.row.col.f32.f16.f16.f32 "          \
                 "{%0,%1,%2,%3},{%4,%5,%6,%7},{%8,%9},{%0,%1,%2,%3};"          \
                 : "+f"((d)[0]), "+f"((d)[1]), "+f"((d)[2]), "+f"((d)[3])      \
                 : "r"((a)[0]), "r"((a)[1]), "r"((a)[2]), "r"((a)[3]),         \
                   "r"((b)[0]), "r"((b)[1]))

__device__ __forceinline__ uint4 cvt8(float4 v0, float4 v1) {
    uint4 o;
    __half2 p;
    p = __floats2half2_rn(v0.x, v0.y); o.x = *(uint32_t*)&p;
    p = __floats2half2_rn(v0.z, v0.w); o.y = *(uint32_t*)&p;
    p = __floats2half2_rn(v1.x, v1.y); o.z = *(uint32_t*)&p;
    p = __floats2half2_rn(v1.z, v1.w); o.w = *(uint32_t*)&p;
    return o;
}

__global__ __launch_bounds__(256, 2) void gemm_tc(const float* __restrict__ X,
                                                  const float* __restrict__ bm) {
    extern __shared__ char smem[];
    const uint32_t sb32 = smem_u32(smem);
    const int tid = threadIdx.x;
    const int hx = blockIdx.x;
    const int row0 = blockIdx.y * 128;
    const int wid = tid >> 5;
    const int lane = tid & 31;
    const int gid = lane >> 2;
    const int tig = lane & 3;
    const int warpM = wid & 3;
    const int warpN = wid >> 2;

    const int r = tid >> 1;
    const int half = tid & 1;
    const bool inb = (row0 + r) < MTOT;
    const size_t aoff = (size_t)(row0 + r) * FIN + half * 32;
    const size_t boff = ((size_t)hx * FOUT + r) * FIN + half * 32;
    const uint32_t srow = (uint32_t)(r * (PADK * 2) + half * 64);
    const float4 zf = make_float4(0.f, 0.f, 0.f, 0.f);

    float acc[2][8][4];
#pragma unroll
    for (int mt = 0; mt < 2; mt++)
#pragma unroll
        for (int nt = 0; nt < 8; nt++)
#pragma unroll
            for (int j = 0; j < 4; j++) acc[mt][nt][j] = 0.f;

    uint4 apre[4];   // A fp16 prefetch (one chunk ahead)

    // ---- prologue: chunk 0 ----
#pragma unroll
    for (int j = 0; j < 4; j++) {
        float4 v0 = inb ? *(const float4*)(X + aoff + j * 8) : zf;
        float4 v1 = inb ? *(const float4*)(X + aoff + j * 8 + 4) : zf;
        apre[j] = cvt8(v0, v1);
        cp16(sb32 + OFF_B + srow + j * 16, d_Bf + boff + j * 8);
    }
    CP_COMMIT();

    for (int kc = 0; kc < FIN / GK; kc++) {
        const int st = kc & 1;
        char* sm = smem + st * STAGE_B;
        const uint32_t smb2 = sb32 + (st ^ 1) * STAGE_B;
        // STS A(kc) from prefetch regs
#pragma unroll
        for (int j = 0; j < 4; j++)
            *(uint4*)(sm + OFF_A + srow + j * 16) = apre[j];
        CP_WAIT0();
        __syncthreads();
        // prefetch chunk kc+1
        if (kc < FIN / GK - 1) {
            size_t ge = (size_t)(kc + 1) * GK;
#pragma unroll
            for (int j = 0; j < 4; j++) {
                float4 v0 = inb ? *(const float4*)(X + aoff + ge + j * 8) : zf;
                float4 v1 = inb ? *(const float4*)(X + aoff + ge + j * 8 + 4) : zf;
                apre[j] = cvt8(v0, v1);
                cp16(smb2 + OFF_B + srow + j * 16, d_Bf + boff + ge + j * 8);
            }
            CP_COMMIT();
        }
        // ---- mma on current stage ----
#pragma unroll
        for (int ks = 0; ks < 4; ks++) {
            const uint32_t kb = (uint32_t)((ks * 16 + tig * 2) * 2);
            uint32_t bf[8][2], af[2][4];
#pragma unroll
            for (int nt = 0; nt < 8; nt++) {
                uint32_t nb = (uint32_t)((warpN * 64 + nt * 8 + gid) * (PADK * 2)) + kb;
                bf[nt][0] = *(const uint32_t*)(sm + OFF_B + nb);
                bf[nt][1] = *(const uint32_t*)(sm + OFF_B + nb + 16);
            }
#pragma unroll
            for (int mt = 0; mt < 2; mt++) {
                uint32_t mb = (uint32_t)((warpM * 32 + mt * 16 + gid) * (PADK * 2)) + kb;
                af[mt][0] = *(const uint32_t*)(sm + OFF_A + mb);
                af[mt][1] = *(const uint32_t*)(sm + OFF_A + mb + 8 * (PADK * 2));
                af[mt][2] = *(const uint32_t*)(sm + OFF_A + mb + 16);
                af[mt][3] = *(const uint32_t*)(sm + OFF_A + mb + 8 * (PADK * 2) + 16);
            }
#pragma unroll
            for (int mt = 0; mt < 2; mt++)
#pragma unroll
                for (int nt = 0; nt < 8; nt++) MMA_F16(acc[mt][nt], af[mt], bf[nt]);
        }
        __syncthreads();
    }

    // ---- epilogue: bias add, fp16 convert, store node-major into d_h ----
    float2 bias[8];
#pragma unroll
    for (int nt = 0; nt < 8; nt++)
        bias[nt] = *(const float2*)(bm + hx * FOUT + warpN * 64 + nt * 8 + tig * 2);

#pragma unroll
    for (int mt = 0; mt < 2; mt++) {
#pragma unroll
        for (int rh = 0; rh < 2; rh++) {
            int gr = row0 + warpM * 32 + mt * 16 + rh * 8 + gid;
            if (gr >= MTOT) continue;
            int bb = gr / NN;
            int n = gr - bb * NN;
            __half* dp = d_h + (size_t)n * CPN + bb * (NH * FOUT) + hx * FOUT
                         + warpN * 64 + tig * 2;
#pragma unroll
            for (int nt = 0; nt < 8; nt++) {
                __half2 v = __floats2half2_rn(acc[mt][nt][rh * 2 + 0] + bias[nt].x,
                                              acc[mt][nt][rh * 2 + 1] + bias[nt].y);
                *(__half2*)(dp + nt * 8) = v;
            }
        }
    }
}

// ---------------- K4: aggregation, block per node, fp16 h, 2-edge ILP ------
#define CHK 128
__global__ __launch_bounds__(256) void aggregate(const int* __restrict__ dst,
                                                 float* __restrict__ out) {
    const int n = blockIdx.x;
    const int r0 = d_rowptr[n];
    const int r1 = d_rowptr[n + 1];
    const int t = threadIdx.x;
    const int head = (t >> 4) & 3;
    __shared__ int sdst[CHK];
    __shared__ float4 sev[CHK];
    const float* evp = (const float*)sev;
    float acc[8];
#pragma unroll
    for (int j = 0; j < 8; j++) acc[j] = 0.f;
    float dacc = 0.f;

    for (int base = r0; base < r1; base += CHK) {
        int cnt = min(CHK, r1 - base);
        __syncthreads();
        if (t < cnt) {
            sdst[t] = dst[base + t];
            sev[t] = d_ev[base + t];
        }
        __syncthreads();
        int i = 0;
#pragma unroll 2
        for (; i + 1 < cnt; i += 2) {
            float w0 = evp[i * 4 + head];
            float w1 = evp[(i + 1) * 4 + head];
            uint4 hv0 = *((const uint4*)(d_h + (size_t)sdst[i] * CPN) + t);
            uint4 hv1 = *((const uint4*)(d_h + (size_t)sdst[i + 1] * CPN) + t);
            const __half2* a2 = (const __half2*)&hv0;
            const __half2* b2 = (const __half2*)&hv1;
#pragma unroll
            for (int j = 0; j < 4; j++) {
                float2 fa = __half22float2(a2[j]);
                float2 fb = __half22float2(b2[j]);
                acc[2 * j]     = fmaf(w0, fa.x, acc[2 * j]);
                acc[2 * j + 1] = fmaf(w0, fa.y, acc[2 * j + 1]);
                acc[2 * j]     = fmaf(w1, fb.x, acc[2 * j]);
                acc[2 * j + 1] = fmaf(w1, fb.y, acc[2 * j + 1]);
            }
            dacc += w0 + w1;
        }
        if (i < cnt) {
            float w = evp[i * 4 + head];
            uint4 hv = *((const uint4*)(d_h + (size_t)sdst[i] * CPN) + t);
            const __half2* a2 = (const __half2*)&hv;
#pragma unroll
            for (int j = 0; j < 4; j++) {
                float2 fa = __half22float2(a2[j]);
                acc[2 * j]     = fmaf(w, fa.x, acc[2 * j]);
                acc[2 * j + 1] = fmaf(w, fa.y, acc[2 * j + 1]);
            }
            dacc += w;
        }
    }
    float inv = (r1 > r0) ? (1.0f / dacc) : 0.f;
    int bb = t >> 6;
    int c0 = (t & 63) * 8;
    float* op = out + (size_t)bb * NN * (NH * FOUT) + (size_t)n * (NH * FOUT) + c0;
    float4 o0 = make_float4(acc[0] * inv, acc[1] * inv, acc[2] * inv, acc[3] * inv);
    float4 o1 = make_float4(acc[4] * inv, acc[5] * inv, acc[6] * inv, acc[7] * inv);
    *(float4*)op = o0;
    *(float4*)(op + 4) = o1;
}

// ---------------------------------------------------------------------------
extern "C" void kernel_launch(void* const* d_in, const int* in_sizes, int n_in,
                              void* d_out, int out_size) {
    const float* x   = (const float*)d_in[0];   // (B, N, 256)
    const float* Wm  = (const float*)d_in[1];   // (H, 256, 128)
    const float* bm  = (const float*)d_in[2];   // (H, 128)
    const float* Wa  = (const float*)d_in[3];   // (H, 256, 1)
    const int*   src = (const int*)d_in[4];     // (E,) sorted
    const int*   dst = (const int*)d_in[5];     // (E,)
    float* out = (float*)d_out;                 // (B, N, 512)

    cudaFuncSetAttribute(gemm_tc, cudaFuncAttributeMaxDynamicSharedMemorySize, SM_TOTAL);

    prep_all<<<516, 256>>>(Wm, bm, Wa);
    node_scores<<<(NN * 32 + 255) / 256, 256>>>(x + (size_t)(NB - 1) * NN * FIN);
    edge_prep<<<(NE + 255) / 256, 256>>>(src, dst);
    dim3 gg(NH, (MTOT + 127) / 128);
    gemm_tc<<<gg, 256, SM_TOTAL>>>(x, bm);
    aggregate<<<NN, 256>>>(dst, out);
}

// round 8
// speedup vs baseline: 1.4878x; 1.4878x over previous
#include <cuda_runtime.h>
#include <cuda_bf16.h>
#include <cuda_fp16.h>
#include <cstdint>

#define NB 4
#define NN 10000
#define NE 170000
#define FIN 256
#define FOUT 128
#define NH 4
#define MTOT (NB*NN)          /* 40000 */
#define CPN (NB*NH*FOUT)      /* 2048 values per node row */
#define LEAKY 0.2f

// ---------------- scratch (static device memory; no allocs allowed) --------
__device__ __half  d_h[(size_t)NN * CPN];      // h fp16, node-major [n][b][head][f] (41 MB)
__device__ float4  d_ev[NE];                   // exp(att) per edge, 4 heads packed
__device__ float4  d_ps[NN];
__device__ float4  d_pd[NN];
__device__ int     d_rowptr[NN + 1];
__device__ float   d_vsrc[NH * FIN];
__device__ float   d_vdst[NH * FIN];
__device__ float   d_csrc[NH];
__device__ float   d_cdst[NH];
// fp16 W transposed to [h][n][k] for the tensor-core GEMM
__device__ __half  d_Bf[NH * FOUT * FIN];

__device__ __forceinline__ uint32_t smem_u32(const void* p) {
    uint32_t a;
    asm("{ .reg .u64 t; cvta.to.shared.u64 t, %1; cvt.u32.u64 %0, t; }" : "=r"(a) : "l"(p));
    return a;
}

// ---------------- K0: W fp16 transpose + attention-vector fold (fused) -----
__global__ void prep_all(const float* __restrict__ Wm, const float* __restrict__ bm,
                         const float* __restrict__ Wa) {
    if (blockIdx.x < 512) {
        int i = blockIdx.x * 256 + threadIdx.x;      // [h][k][f]
        int h = i >> 15;
        int rem = i & 32767;
        int k = rem >> 7;
        int f = rem & 127;
        size_t o = ((size_t)h * FOUT + f) * FIN + k; // [h][n][k]
        d_Bf[o] = __float2half_rn(Wm[i]);
        return;
    }
    int h = blockIdx.x - 512;
    int t = threadIdx.x;
    __shared__ float asrc[FOUT], adst[FOUT];
    if (t < FOUT) {
        asrc[t] = Wa[h * 2 * FOUT + t];
        adst[t] = Wa[h * 2 * FOUT + FOUT + t];
    }
    __syncthreads();
    const float* w = Wm + (size_t)h * FIN * FOUT + (size_t)t * FOUT;
    float s1 = 0.f, s2 = 0.f;
#pragma unroll 8
    for (int f = 0; f < FOUT; f++) {
        float wv = w[f];
        s1 += wv * asrc[f];
        s2 += wv * adst[f];
    }
    d_vsrc[h * FIN + t] = s1;
    d_vdst[h * FIN + t] = s2;
    if (t == 0) {
        float c1 = 0.f, c2 = 0.f;
        for (int f = 0; f < FOUT; f++) {
            float bv = bm[h * FOUT + f];
            c1 += bv * asrc[f];
            c2 += bv * adst[f];
        }
        d_csrc[h] = c1;
        d_cdst[h] = c2;
    }
}

// ---------------- K1: per-node scores, warp per node -----------------------
__global__ void node_scores(const float* __restrict__ Xl) {
    int gw = (blockIdx.x * blockDim.x + threadIdx.x) >> 5;
    int lane = threadIdx.x & 31;
    if (gw >= NN) return;
    const float* xr = Xl + (size_t)gw * FIN;
    float xv[8];
#pragma unroll
    for (int i = 0; i < 8; i++) xv[i] = xr[lane + 32 * i];
    float ps[NH], pd[NH];
#pragma unroll
    for (int h = 0; h < NH; h++) {
        float s1 = 0.f, s2 = 0.f;
#pragma unroll
        for (int i = 0; i < 8; i++) {
            int k = lane + 32 * i;
            s1 += xv[i] * d_vsrc[h * FIN + k];
            s2 += xv[i] * d_vdst[h * FIN + k];
        }
#pragma unroll
        for (int o = 16; o > 0; o >>= 1) {
            s1 += __shfl_down_sync(0xffffffffu, s1, o);
            s2 += __shfl_down_sync(0xffffffffu, s2, o);
        }
        ps[h] = s1;
        pd[h] = s2;
    }
    if (lane == 0) {
        d_ps[gw] = make_float4(ps[0] + d_csrc[0], ps[1] + d_csrc[1],
                               ps[2] + d_csrc[2], ps[3] + d_csrc[3]);
        d_pd[gw] = make_float4(pd[0] + d_cdst[0], pd[1] + d_cdst[1],
                               pd[2] + d_cdst[2], pd[3] + d_cdst[3]);
    }
}

// ---------------- K2: per-edge exp + CSR row_ptr (fused) -------------------
__device__ __forceinline__ float att_act(float s) {
    float lr = s > 0.f ? s : LEAKY * s;
    lr = fminf(fmaxf(lr, -2.f), 2.f);
    return expf(lr);
}

__global__ void edge_prep(const int* __restrict__ src, const int* __restrict__ dst) {
    int e = blockIdx.x * blockDim.x + threadIdx.x;
    if (e >= NE) return;
    int cur = src[e];
    float4 a = d_ps[cur];
    float4 b = d_pd[dst[e]];
    d_ev[e] = make_float4(att_act(a.x + b.x), att_act(a.y + b.y),
                          att_act(a.z + b.z), att_act(a.w + b.w));
    int prev = (e == 0) ? -1 : src[e - 1];
    for (int n = prev + 1; n <= cur; n++) d_rowptr[n] = e;
    if (e == NE - 1)
        for (int n = cur + 1; n <= NN; n++) d_rowptr[n] = NE;
}

// ---------------- K3: single-pass fp16 GEMM, ldmatrix fragments ------------
// CTA: 256 thr / 8 warps; tile M=128 x N=128 (one head); K chunk = 64.
// R6 structure (single buffer, no pipeline) + LDSM fragment loads.
#define GK 64
#define PADK 72                       /* padded k-stride (fp16) -> 144B rows  */
#define ROWB (PADK * 2)               /* 144 bytes */
#define TILE_B (128 * ROWB)           /* 18432 bytes per smem tile */
#define OFF_A 0
#define OFF_B (TILE_B)
#define SM_TOTAL (2 * TILE_B)         /* 36864 */

#define MMA_F16(d, a, b)                                                       \
    asm volatile("mma.sync.aligned.m16n8k16.row.col.f32.f16.f16.f32 "          \
                 "{%0,%1,%2,%3},{%4,%5,%6,%7},{%8,%9},{%0,%1,%2,%3};"          \
                 : "+f"((d)[0]), "+f"((d)[1]), "+f"((d)[2]), "+f"((d)[3])      \
                 : "r"((a)[0]), "r"((a)[1]), "r"((a)[2]), "r"((a)[3]),         \
                   "r"((b)[0]), "r"((b)[1]))

#define LDSM4(r0, r1, r2, r3, addr)                                            \
    asm volatile("ldmatrix.sync.aligned.m8n8.x4.shared.b16 {%0,%1,%2,%3},[%4];"\
                 : "=r"(r0), "=r"(r1), "=r"(r2), "=r"(r3) : "r"(addr))

__global__ __launch_bounds__(256) void gemm_tc(const float* __restrict__ X,
                                               const float* __restrict__ bm) {
    extern __shared__ char smem[];
    const uint32_t sb32 = smem_u32(smem);
    const int tid = threadIdx.x;
    const int hx = blockIdx.x;
    const int row0 = blockIdx.y * 128;
    const int wid = tid >> 5;
    const int lane = tid & 31;
    const int gid = lane >> 2;
    const int tig = lane & 3;
    const int warpM = wid & 3;
    const int warpN = wid >> 2;

    // gmem->smem mapping (same as R6)
    const int r = tid >> 1;
    const int half = tid & 1;
    const bool inb = (row0 + r) < MTOT;
    const size_t aoff = (size_t)(row0 + r) * FIN + half * 32;
    const size_t boff = ((size_t)hx * FOUT + r) * FIN + half * 32;
    const uint32_t srow = (uint32_t)(r * ROWB + half * 64);
    const float4 zf = make_float4(0.f, 0.f, 0.f, 0.f);

    // ldmatrix per-lane base addresses
    const uint32_t aRow = (uint32_t)(warpM * 32 + (lane & 15));
    const uint32_t aKof = (uint32_t)((lane >> 4) * 8);
    const uint32_t aBase = sb32 + OFF_A + aRow * ROWB + aKof * 2;
    const uint32_t bN = (uint32_t)(warpN * 64 + (lane & 7) + ((lane & 16) ? 8 : 0));
    const uint32_t bKof = (uint32_t)((lane & 8) ? 8 : 0);
    const uint32_t bBase = sb32 + OFF_B + bN * ROWB + bKof * 2;

    float acc[2][8][4];
#pragma unroll
    for (int mt = 0; mt < 2; mt++)
#pragma unroll
        for (int nt = 0; nt < 8; nt++)
#pragma unroll
            for (int j = 0; j < 4; j++) acc[mt][nt][j] = 0.f;

    for (int kc = 0; kc < FIN / GK; kc++) {
        if (kc) __syncthreads();
#pragma unroll
        for (int j = 0; j < 4; j++) {
            size_t ge = (size_t)kc * GK + j * 8;
            uint32_t so = srow + j * 16;
            float4 v0 = inb ? *(const float4*)(X + aoff + ge) : zf;
            float4 v1 = inb ? *(const float4*)(X + aoff + ge + 4) : zf;
            uint4 ah;
            __half2 p;
            p = __floats2half2_rn(v0.x, v0.y); ah.x = *(uint32_t*)&p;
            p = __floats2half2_rn(v0.z, v0.w); ah.y = *(uint32_t*)&p;
            p = __floats2half2_rn(v1.x, v1.y); ah.z = *(uint32_t*)&p;
            p = __floats2half2_rn(v1.z, v1.w); ah.w = *(uint32_t*)&p;
            uint4 wv = *(const uint4*)(d_Bf + boff + ge);
            *(uint4*)(smem + OFF_A + so) = ah;
            *(uint4*)(smem + OFF_B + so) = wv;
        }
        __syncthreads();
#pragma unroll
        for (int ks = 0; ks < 4; ks++) {
            const uint32_t kB = (uint32_t)(ks * 16 * 2);
            uint32_t af[2][4], bf[8][2];
#pragma unroll
            for (int mt = 0; mt < 2; mt++)
                LDSM4(af[mt][0], af[mt][1], af[mt][2], af[mt][3],
                      aBase + (uint32_t)(mt * 16 * ROWB) + kB);
#pragma unroll
            for (int p4 = 0; p4 < 4; p4++)
                LDSM4(bf[2 * p4][0], bf[2 * p4][1], bf[2 * p4 + 1][0], bf[2 * p4 + 1][1],
                      bBase + (uint32_t)(p4 * 16 * ROWB) + kB);
#pragma unroll
            for (int mt = 0; mt < 2; mt++)
#pragma unroll
                for (int nt = 0; nt < 8; nt++) MMA_F16(acc[mt][nt], af[mt], bf[nt]);
        }
    }

    // ---- epilogue: bias add, fp16 convert, store node-major into d_h ----
    float2 bias[8];
#pragma unroll
    for (int nt = 0; nt < 8; nt++)
        bias[nt] = *(const float2*)(bm + hx * FOUT + warpN * 64 + nt * 8 + tig * 2);

#pragma unroll
    for (int mt = 0; mt < 2; mt++) {
#pragma unroll
        for (int rh = 0; rh < 2; rh++) {
            int gr = row0 + warpM * 32 + mt * 16 + rh * 8 + gid;
            if (gr >= MTOT) continue;
            int bb = gr / NN;
            int n = gr - bb * NN;
            __half* dp = d_h + (size_t)n * CPN + bb * (NH * FOUT) + hx * FOUT
                         + warpN * 64 + tig * 2;
#pragma unroll
            for (int nt = 0; nt < 8; nt++) {
                __half2 v = __floats2half2_rn(acc[mt][nt][rh * 2 + 0] + bias[nt].x,
                                              acc[mt][nt][rh * 2 + 1] + bias[nt].y);
                *(__half2*)(dp + nt * 8) = v;
            }
        }
    }
}

// ---------------- K4: aggregation, block per node, fp16 h, 2-edge ILP ------
#define CHK 128
__global__ __launch_bounds__(256) void aggregate(const int* __restrict__ dst,
                                                 float* __restrict__ out) {
    const int n = blockIdx.x;
    const int r0 = d_rowptr[n];
    const int r1 = d_rowptr[n + 1];
    const int t = threadIdx.x;
    const int head = (t >> 4) & 3;
    __shared__ int sdst[CHK];
    __shared__ float4 sev[CHK];
    const float* evp = (const float*)sev;
    float acc[8];
#pragma unroll
    for (int j = 0; j < 8; j++) acc[j] = 0.f;
    float dacc = 0.f;

    for (int base = r0; base < r1; base += CHK) {
        int cnt = min(CHK, r1 - base);
        __syncthreads();
        if (t < cnt) {
            sdst[t] = dst[base + t];
            sev[t] = d_ev[base + t];
        }
        __syncthreads();
        int i = 0;
#pragma unroll 2
        for (; i + 1 < cnt; i += 2) {
            float w0 = evp[i * 4 + head];
            float w1 = evp[(i + 1) * 4 + head];
            uint4 hv0 = *((const uint4*)(d_h + (size_t)sdst[i] * CPN) + t);
            uint4 hv1 = *((const uint4*)(d_h + (size_t)sdst[i + 1] * CPN) + t);
            const __half2* a2 = (const __half2*)&hv0;
            const __half2* b2 = (const __half2*)&hv1;
#pragma unroll
            for (int j = 0; j < 4; j++) {
                float2 fa = __half22float2(a2[j]);
                float2 fb = __half22float2(b2[j]);
                acc[2 * j]     = fmaf(w0, fa.x, acc[2 * j]);
                acc[2 * j + 1] = fmaf(w0, fa.y, acc[2 * j + 1]);
                acc[2 * j]     = fmaf(w1, fb.x, acc[2 * j]);
                acc[2 * j + 1] = fmaf(w1, fb.y, acc[2 * j + 1]);
            }
            dacc += w0 + w1;
        }
        if (i < cnt) {
            float w = evp[i * 4 + head];
            uint4 hv = *((const uint4*)(d_h + (size_t)sdst[i] * CPN) + t);
            const __half2* a2 = (const __half2*)&hv;
#pragma unroll
            for (int j = 0; j < 4; j++) {
                float2 fa = __half22float2(a2[j]);
                acc[2 * j]     = fmaf(w, fa.x, acc[2 * j]);
                acc[2 * j + 1] = fmaf(w, fa.y, acc[2 * j + 1]);
            }
            dacc += w;
        }
    }
    float inv = (r1 > r0) ? (1.0f / dacc) : 0.f;
    int bb = t >> 6;
    int c0 = (t & 63) * 8;
    float* op = out + (size_t)bb * NN * (NH * FOUT) + (size_t)n * (NH * FOUT) + c0;
    float4 o0 = make_float4(acc[0] * inv, acc[1] * inv, acc[2] * inv, acc[3] * inv);
    float4 o1 = make_float4(acc[4] * inv, acc[5] * inv, acc[6] * inv, acc[7] * inv);
    *(float4*)op = o0;
    *(float4*)(op + 4) = o1;
}

// ---------------------------------------------------------------------------
extern "C" void kernel_launch(void* const* d_in, const int* in_sizes, int n_in,
                              void* d_out, int out_size) {
    const float* x   = (const float*)d_in[0];   // (B, N, 256)
    const float* Wm  = (const float*)d_in[1];   // (H, 256, 128)
    const float* bm  = (const float*)d_in[2];   // (H, 128)
    const float* Wa  = (const float*)d_in[3];   // (H, 256, 1)
    const int*   src = (const int*)d_in[4];     // (E,) sorted
    const int*   dst = (const int*)d_in[5];     // (E,)
    float* out = (float*)d_out;                 // (B, N, 512)

    cudaFuncSetAttribute(gemm_tc, cudaFuncAttributeMaxDynamicSharedMemorySize, SM_TOTAL);

    prep_all<<<516, 256>>>(Wm, bm, Wa);
    node_scores<<<(NN * 32 + 255) / 256, 256>>>(x + (size_t)(NB - 1) * NN * FIN);
    edge_prep<<<(NE + 255) / 256, 256>>>(src, dst);
    dim3 gg(NH, (MTOT + 127) / 128);
    gemm_tc<<<gg, 256, SM_TOTAL>>>(x, bm);
    aggregate<<<NN, 256>>>(dst, out);
}